// round 5
// baseline (speedup 1.0000x reference)
#include <cuda_runtime.h>
#include <math.h>

#define T_DATA 40000
#define SUB    32
#define E_E    2000
#define E_I    400
#define TNO    200
#define NCOS   17
#define FILT_OFF (2*T_DATA)

#define PI_F   3.14159274f      // float32(pi), matches jnp
#define HPI_F  1.5707964f       // float32(pi/2)

// ---------------- scratch (no allocation allowed) ----------------
__device__ float g_syn_e[(size_t)T_DATA*SUB];
__device__ float g_syn_i[(size_t)T_DATA*SUB];
__device__ float g_syn  [(size_t)T_DATA*SUB];
__device__ float g_ke[TNO*SUB];   // transposed [tau][s]
__device__ float g_ki[TNO*SUB];
__device__ float g_hk[TNO];
__device__ float g_ok[TNO];
// one-hot fast tables: {byte_offset = s*4, float_bits(w)} per column
__device__ int2  g_etab[E_E];
__device__ int2  g_itab[E_I];
__device__ int   g_onehot;
// generic fallback CSR (row-major, cold)
__device__ int   g_ecnt[E_E];
__device__ int   g_esub[E_E*SUB];
__device__ float g_ew  [E_E*SUB];
__device__ int   g_icnt[E_I];
__device__ int   g_isub[E_I*SUB];
__device__ float g_iw  [E_I*SUB];
__device__ int   g_ch_cnt[SUB];
__device__ int   g_ch_idx[SUB*SUB];
__device__ float g_ch_w[SUB*SUB];

// ---------------- kZ: zero accumulators + reset one-hot flag (every replay) ----------------
__global__ void kZ_zero() {
    int gid = blockIdx.x * blockDim.x + threadIdx.x;
    int nth = gridDim.x * blockDim.x;
    if (gid == 0) g_onehot = 1;
    float4 z4 = make_float4(0.f, 0.f, 0.f, 0.f);
    float4* ze = (float4*)g_syn_e;
    float4* zi = (float4*)g_syn_i;
    for (int i = gid; i < T_DATA*SUB/4; i += nth) { ze[i] = z4; zi[i] = z4; }
}

// ---------------- kC: fast tables + generic CSR + dendrite children ----------------
__global__ void kC_csr(const float* __restrict__ Ce, const float* __restrict__ Ci,
                       const float* __restrict__ C_den, const float* __restrict__ W_sub) {
    int e = blockIdx.x * blockDim.x + threadIdx.x;
    if (e < E_E) {
        int c = 0; int s0 = 0; float w0 = 0.f;
        for (int s = 0; s < SUB; s++) {
            float w = Ce[(size_t)s * E_E + e];
            if (w != 0.f) {
                if (c == 0) { s0 = s; w0 = w; }
                g_esub[e*SUB + c] = s; g_ew[e*SUB + c] = w; c++;
            }
        }
        g_ecnt[e] = c;
        g_etab[e] = make_int2(s0 * 4, __float_as_int(w0));
        if (c > 1) atomicAnd(&g_onehot, 0);
    }
    if (e < E_I) {
        int c = 0; int s0 = 0; float w0 = 0.f;
        for (int s = 0; s < SUB; s++) {
            float w = Ci[(size_t)s * E_I + e];
            if (w != 0.f) {
                if (c == 0) { s0 = s; w0 = w; }
                g_isub[e*SUB + c] = s; g_iw[e*SUB + c] = w; c++;
            }
        }
        g_icnt[e] = c;
        g_itab[e] = make_int2(s0 * 4, __float_as_int(w0));
        if (c > 1) atomicAnd(&g_onehot, 0);
    }
    if (e < SUB) {   // children lists, weights pre-multiplied by exp(W_sub[child])
        int c = 0;
        for (int j = 0; j < SUB; j++) {
            float w = C_den[e*SUB + j];
            if (w != 0.f) {
                g_ch_idx[e*SUB + c] = j;
                g_ch_w[e*SUB + c]   = w * expf(W_sub[j]);
                c++;
            }
        }
        g_ch_cnt[e] = c;
    }
}

// ---------------- kK: alpha/hist/out kernels + out_filters section of dout ----------------
__global__ void kK_kernels(const float* __restrict__ Tau_syn, const float* __restrict__ Delta_syn,
                           const float* __restrict__ W_syn,   const float* __restrict__ W_hist,
                           const float* __restrict__ Tau_out, const float* __restrict__ W_out,
                           float* __restrict__ dout) {
    int gid = blockIdx.x * blockDim.x + threadIdx.x;
    int nth = gridDim.x * blockDim.x;

    for (int i = gid; i < SUB * TNO; i += nth) {
        int s = i / TNO, tau = i % TNO;
        float t = (float)tau;
        float te  = fmaxf(t - expf(Delta_syn[s*2 + 0]), 0.f);
        float tte = te / expf(Tau_syn[s*2 + 0]);
        float ek  = tte * expf(-tte) * expf(W_syn[s*2 + 0]);
        float ti  = fmaxf(t - expf(Delta_syn[s*2 + 1]), 0.f);
        float tti = ti / expf(Tau_syn[s*2 + 1]);
        float ik  = -tti * expf(-tti) * expf(W_syn[s*2 + 1]);
        g_ke[tau*SUB + s] = ek;
        g_ki[tau*SUB + s] = ik;
        dout[FILT_OFF + s*TNO + tau]           = ek;
        dout[FILT_OFF + SUB*TNO + s*TNO + tau] = ik;
    }

    for (int tau = gid; tau < TNO; tau += nth) {
        float raw = 4.f * logf((float)tau + 1.f);
        float hk = 0.f;
        #pragma unroll
        for (int n = 0; n < NCOS; n++) {
            float phi = HPI_F * (float)n;
            if (raw >= phi - PI_F && raw <= phi + PI_F)
                hk -= expf(W_hist[n]) * (0.5f * cosf(raw - phi) + 0.5f);
        }
        g_hk[tau] = hk;
        dout[FILT_OFF + 2*SUB*TNO + tau] = hk;

        float tto = (float)tau / expf(Tau_out[0]);
        g_ok[tau] = tto * expf(-tto) * expf(W_out[0]);
    }
}

// ---------------- K1: branch-free predicated spike scatter ----------------
// if (v != 0): {off,w} = *tab; red.global dst[off] += v*w  — no BSSY, masked lanes free.
// NOTE: no "memory" clobber — volatile keeps the RED, but the compiler is free
// to pipeline unrelated LDGs across it (that freedom is the whole point).
__device__ __forceinline__ void spike_add(float v, const int2* tab, float* dst) {
    asm volatile(
        "{\n\t"
        ".reg .pred p;\n\t"
        ".reg .b32 ro, rw;\n\t"
        ".reg .f32 fv;\n\t"
        ".reg .b64 ra;\n\t"
        "setp.ne.f32 p, %0, 0f00000000;\n\t"
        "@p ld.global.nc.v2.b32 {ro, rw}, [%1];\n\t"
        "@p cvt.u64.u32 ra, ro;\n\t"
        "@p add.s64 ra, ra, %2;\n\t"
        "@p mov.b32 fv, rw;\n\t"
        "@p mul.f32 fv, %0, fv;\n\t"
        "@p red.global.add.f32 [ra], fv;\n\t"
        "}" :: "f"(v), "l"(tab), "l"(dst));
}

__global__ void __launch_bounds__(256, 4) k1_proj(const float* __restrict__ Se,
                                                  const float* __restrict__ Si) {
    int gt  = blockIdx.x * blockDim.x + threadIdx.x;
    int nth = gridDim.x * blockDim.x;

    // ---- excitatory: 20,000,000 quads (500 quads per t-row) ----
    {
        const float4* p = (const float4*)Se;
        const int NQ = T_DATA * (E_E/4);
        #pragma unroll 4
        for (int q = gt; q < NQ; q += nth) {
            float4 v = __ldg(p + q);
            unsigned t = (unsigned)q / 500u;
            int e0 = (q - (int)t * 500) * 4;
            float* dst = g_syn_e + (size_t)t * SUB;
            const int2* tb = g_etab + e0;
            spike_add(v.x, tb + 0, dst);
            spike_add(v.y, tb + 1, dst);
            spike_add(v.z, tb + 2, dst);
            spike_add(v.w, tb + 3, dst);
        }
    }
    // ---- inhibitory: 4,000,000 quads (100 quads per t-row) ----
    {
        const float4* p = (const float4*)Si;
        const int NQ = T_DATA * (E_I/4);
        #pragma unroll 4
        for (int q = gt; q < NQ; q += nth) {
            float4 v = __ldg(p + q);
            unsigned t = (unsigned)q / 100u;
            int e0 = (q - (int)t * 100) * 4;
            float* dst = g_syn_i + (size_t)t * SUB;
            const int2* tb = g_itab + e0;
            spike_add(v.x, tb + 0, dst);
            spike_add(v.y, tb + 1, dst);
            spike_add(v.z, tb + 2, dst);
            spike_add(v.w, tb + 3, dst);
        }
    }

    // ---- generic fallback for non-one-hot columns (never taken for this data) ----
    if (__ldg(&g_onehot) == 0) {
        for (int e = gt; e < E_E; e += nth) {
            int c = g_ecnt[e];
            if (c > 1) {
                for (int t = 0; t < T_DATA; t++) {
                    float v = Se[(size_t)t * E_E + e];
                    if (v != 0.f)
                        for (int k = 1; k < c; k++)
                            atomicAdd(g_syn_e + (size_t)t*SUB + g_esub[e*SUB+k], v * g_ew[e*SUB+k]);
                }
            }
        }
        for (int e = gt; e < E_I; e += nth) {
            int c = g_icnt[e];
            if (c > 1) {
                for (int t = 0; t < T_DATA; t++) {
                    float v = Si[(size_t)t * E_I + e];
                    if (v != 0.f)
                        for (int k = 1; k < c; k++)
                            atomicAdd(g_syn_i + (size_t)t*SUB + g_isub[e*SUB+k], v * g_iw[e*SUB+k]);
                }
            }
        }
    }
}

// ---------------- K3: depthwise causal conv via fma.rn.f32x2 ----------------
__device__ __forceinline__ void ffma2(unsigned long long& d,
                                      unsigned long long a, unsigned long long b) {
    asm("fma.rn.f32x2 %0, %1, %2, %0;" : "+l"(d) : "l"(a), "l"(b));
}

#define TB3   256
#define ROWS3 (TB3 + TNO)                      // 456
#define SMEM3 (ROWS3 * SUB * 2 * (int)sizeof(float))  // 116736 B

__global__ void __launch_bounds__(512) k3_conv() {
    extern __shared__ float sh[];
    float* se_sh = sh;                   // [ROWS3][32]
    float* si_sh = sh + ROWS3 * SUB;

    int t0 = blockIdx.x * TB3;

    {
        const float4* ge = (const float4*)g_syn_e;
        const float4* gi = (const float4*)g_syn_i;
        float4* de = (float4*)se_sh;
        float4* di = (float4*)si_sh;
        float4 z = make_float4(0.f, 0.f, 0.f, 0.f);
        for (int l = threadIdx.x; l < ROWS3 * 8; l += 512) {
            int row = l >> 3, c = l & 7;
            int g = t0 - TNO + row;
            if (g >= 0 && g < T_DATA) { de[l] = ge[g*8 + c]; di[l] = gi[g*8 + c]; }
            else                      { de[l] = z;           di[l] = z;           }
        }
    }
    __syncthreads();

    int lane  = threadIdx.x & 31, wid = threadIdx.x >> 5;
    int p     = lane & 15;               // channel pair (ch 2p, 2p+1)
    int tslot = lane >> 4;
    int ob    = wid * 16 + tslot * 8;    // output-time base within block

    const unsigned long long* se2 = (const unsigned long long*)se_sh;
    const unsigned long long* si2 = (const unsigned long long*)si_sh;
    const unsigned long long* ke2 = (const unsigned long long*)g_ke;
    const unsigned long long* ki2 = (const unsigned long long*)g_ki;

    unsigned long long acc[8];
    #pragma unroll
    for (int i = 0; i < 8; i++) acc[i] = 0ull;

    for (int tb = 0; tb < TNO; tb += 8) {
        int rbase = ob + 192 - tb;
        unsigned long long kk[8], ss[15];

        #pragma unroll
        for (int j = 0; j < 8; j++) kk[j] = __ldg(&ke2[(tb + j)*16 + p]);
        #pragma unroll
        for (int m = 0; m < 15; m++) ss[m] = se2[(rbase + m)*16 + p];
        #pragma unroll
        for (int i = 0; i < 8; i++)
            #pragma unroll
            for (int j = 0; j < 8; j++)
                ffma2(acc[i], kk[j], ss[7 + i - j]);

        #pragma unroll
        for (int j = 0; j < 8; j++) kk[j] = __ldg(&ki2[(tb + j)*16 + p]);
        #pragma unroll
        for (int m = 0; m < 15; m++) ss[m] = si2[(rbase + m)*16 + p];
        #pragma unroll
        for (int i = 0; i < 8; i++)
            #pragma unroll
            for (int j = 0; j < 8; j++)
                ffma2(acc[i], kk[j], ss[7 + i - j]);
    }

    unsigned long long* out2 = (unsigned long long*)g_syn;
    #pragma unroll
    for (int i = 0; i < 8; i++) {
        int t = t0 + ob + i;
        if (t < T_DATA) out2[(size_t)t*16 + p] = acc[i];
    }
}

// ---------------- K4: hist filter + sparse tree walk + heaviside -> Z_out ----------------
#define TB4 256
#define SMEM4 ((SUB*TB4*2 + (TB4+TNO) + TNO + SUB) * (int)sizeof(float))  // 68288 B

__global__ void __launch_bounds__(TB4) k4_tree(const float* __restrict__ Z,
                                               const float* __restrict__ Theta,
                                               float* __restrict__ dout) {
    extern __shared__ float sh[];
    float* sub_sh = sh;                       // [node][tid]
    float* syn_sh = sub_sh + SUB*TB4;         // [node][tid]
    float* Zsh    = syn_sh + SUB*TB4;         // TB4 + TNO
    float* hk     = Zsh + (TB4 + TNO);        // TNO
    float* Th     = hk + TNO;                 // SUB

    int t0  = blockIdx.x * TB4;
    int tid = threadIdx.x;

    for (int l = tid; l < TB4 + TNO; l += TB4) {
        int g = t0 - TNO + l;
        Zsh[l] = (g >= 0 && g < T_DATA) ? Z[g] : 0.f;
    }
    for (int l = tid; l < TNO; l += TB4) hk[l] = g_hk[l];
    if (tid < SUB) Th[tid] = Theta[tid];

    int t = t0 + tid;
    if (t < T_DATA) {
        const float4* sp = (const float4*)(g_syn + (size_t)t * SUB);
        #pragma unroll
        for (int i = 0; i < 8; i++) {
            float4 v = sp[i];
            syn_sh[(i*4+0)*TB4 + tid] = v.x;
            syn_sh[(i*4+1)*TB4 + tid] = v.y;
            syn_sh[(i*4+2)*TB4 + tid] = v.z;
            syn_sh[(i*4+3)*TB4 + tid] = v.w;
        }
    }
    __syncthreads();
    if (t >= T_DATA) return;

    float hist = 0.f;
    #pragma unroll 4
    for (int tau = 0; tau < TNO; tau++)
        hist = fmaf(hk[tau], Zsh[tid + TNO - 1 - tau], hist);

    for (int idx = SUB - 1; idx >= 1; --idx) {
        float a = syn_sh[idx*TB4 + tid] + Th[idx];
        int c = g_ch_cnt[idx];
        for (int k = 0; k < c; k++) {
            int ci = g_ch_idx[idx*SUB + k];
            a = fmaf(g_ch_w[idx*SUB + k], sub_sh[ci*TB4 + tid], a);
        }
        sub_sh[idx*TB4 + tid] = tanhf(a);
    }

    float leaf = 0.f;
    {
        int c = g_ch_cnt[0];
        for (int k = 0; k < c; k++)
            leaf = fmaf(g_ch_w[k], sub_sh[g_ch_idx[k]*TB4 + tid], leaf);
    }

    float zin = hist + syn_sh[tid] + leaf + Th[0];
    dout[T_DATA + t] = (zin > 0.f) ? 1.f : 0.f;
}

// ---------------- K5: output alpha-kernel conv of Z_out -> V_out ----------------
__global__ void k5_vout(float* __restrict__ dout) {
    __shared__ float Zsh[256 + TNO];
    __shared__ float ok[TNO];
    const float* zo = dout + T_DATA;

    int t0 = blockIdx.x * 256;
    for (int l = threadIdx.x; l < 256 + TNO; l += 256) {
        int g = t0 - TNO + l;
        Zsh[l] = (g >= 0 && g < T_DATA) ? zo[g] : 0.f;
    }
    for (int l = threadIdx.x; l < TNO; l += 256) ok[l] = g_ok[l];
    __syncthreads();

    int t = t0 + threadIdx.x;
    if (t >= T_DATA) return;

    float v = 0.f;
    int tl = threadIdx.x;
    #pragma unroll 4
    for (int tau = 0; tau < TNO; tau++)
        v = fmaf(ok[tau], Zsh[tl + TNO - 1 - tau], v);
    dout[t] = v;
}

// ---------------- launcher ----------------
extern "C" void kernel_launch(void* const* d_in, const int* in_sizes, int n_in,
                              void* d_out, int out_size) {
    const float* Se        = (const float*)d_in[0];
    const float* Si        = (const float*)d_in[1];
    const float* Z         = (const float*)d_in[2];
    const float* Cden      = (const float*)d_in[3];
    const float* Ce        = (const float*)d_in[4];
    const float* Ci        = (const float*)d_in[5];
    const float* Tau_syn   = (const float*)d_in[6];
    const float* Delta_syn = (const float*)d_in[7];
    const float* W_syn     = (const float*)d_in[8];
    const float* W_sub     = (const float*)d_in[9];
    const float* W_hist    = (const float*)d_in[10];
    const float* Theta     = (const float*)d_in[11];
    const float* Tau_out   = (const float*)d_in[12];
    const float* W_out     = (const float*)d_in[13];
    float* out = (float*)d_out;

    kZ_zero<<<512, 256>>>();
    kC_csr<<<(E_E + 255) / 256, 256>>>(Ce, Ci, Cden, W_sub);
    kK_kernels<<<32, 256>>>(Tau_syn, Delta_syn, W_syn, W_hist, Tau_out, W_out, out);
    k1_proj<<<2048, 256>>>(Se, Si);     // hot kernel

    cudaFuncSetAttribute(k3_conv, cudaFuncAttributeMaxDynamicSharedMemorySize, SMEM3);
    k3_conv<<<(T_DATA + TB3 - 1) / TB3, 512, SMEM3>>>();

    cudaFuncSetAttribute(k4_tree, cudaFuncAttributeMaxDynamicSharedMemorySize, SMEM4);
    k4_tree<<<(T_DATA + TB4 - 1) / TB4, TB4, SMEM4>>>(Z, Theta, out);

    k5_vout<<<(T_DATA + 255) / 256, 256>>>(out);
}